// round 8
// baseline (speedup 1.0000x reference)
#include <cuda_runtime.h>
#include <cuda_bf16.h>

#define NN 1024
#define HID 256
#define NH 8
#define HD 32
#define NE 16384

#define TBL_N 8192
#define TBL_MAX 24.0f
#define TBL_SCALE ((float)(TBL_N - 1) / TBL_MAX)

typedef unsigned long long ull;

// ---- packed fp32x2 helpers (kept for GEMMs) ---------------------------------
__device__ __forceinline__ ull pack2(float lo, float hi) {
    ull r; asm("mov.b64 %0, {%1, %2};" : "=l"(r) : "f"(lo), "f"(hi)); return r;
}
__device__ __forceinline__ float2 unpack2(ull v) {
    float2 f; asm("mov.b64 {%0, %1}, %2;" : "=f"(f.x), "=f"(f.y) : "l"(v)); return f;
}
__device__ __forceinline__ void fma2(ull& d, ull a, ull b) {
    asm("fma.rn.f32x2 %0, %1, %2, %0;" : "+l"(d) : "l"(a), "l"(b));
}

// ---------------- scratch (static device memory; no allocations) -------------
__device__ float    g_q[NN * HID];
__device__ float    g_k[NN * HID];
__device__ float    g_v[NN * HID];
__device__ float    g_gateh[NN * 4 * HID];
__device__ float    g_gate[NN * 2];
__device__ unsigned g_adj[NN * 32];
__device__ unsigned g_pa[NN * 32];
__device__ unsigned g_pb[NN * 32];
__device__ float    g_ttab[16];            // [path_val(0/1)][head]
__device__ float    g_tbl[NH * TBL_N];     // geo MLP lookup table [h][i]
__device__ float    g_attnout[NN * HID];
__device__ float    g_proj[NN * HID];
__device__ int      g_idx64;

// ---------------- edge index dtype detection ---------------------------------
__global__ void detect_kernel(const unsigned* __restrict__ w) {
    if (threadIdx.x == 0) {
        int is64 = 1;
        for (int i = 0; i < 64; i++) {
            if (w[2 * i + 1] != 0u) { is64 = 0; break; }
        }
        g_idx64 = is64;
    }
}

__global__ void zero_adj_kernel() {
    int i = blockIdx.x * 256 + threadIdx.x;
    if (i < NN * 32) g_adj[i] = 0u;
}

__global__ void scatter_edges_kernel(const void* __restrict__ edges) {
    int e = blockIdx.x * blockDim.x + threadIdx.x;
    if (e >= NE) return;
    int s, d;
    if (g_idx64) {
        const long long* p = (const long long*)edges;
        s = (int)p[e];
        d = (int)p[NE + e];
    } else {
        const int* p = (const int*)edges;
        s = p[e];
        d = p[NE + e];
    }
    atomicOr(&g_adj[s * 32 + (d >> 5)], 1u << (d & 31));
}

// path = min(path, path @ adj): binary reachability step on bitsets.
#define LIST_CAP 512
__global__ __launch_bounds__(256) void path_round_kernel(int r) {
    const unsigned* in = (r == 0) ? g_adj : ((r == 1) ? g_pa : g_pb);
    unsigned* out = (r == 1) ? g_pb : g_pa;
    __shared__ unsigned short lists[8][LIST_CAP];
    int warp = threadIdx.x >> 5, lane = threadIdx.x & 31;
    int row = blockIdx.x * 8 + warp;
    unsigned w = in[row * 32 + lane];
    int c = __popc(w);
    int pre = c;
#pragma unroll
    for (int o = 1; o < 32; o <<= 1) {
        int x = __shfl_up_sync(~0u, pre, o);
        if (lane >= o) pre += x;
    }
    int total = __shfl_sync(~0u, pre, 31);
    unsigned acc = 0u;
    if (total <= LIST_CAP) {
        int k = pre - c;
        unsigned tmp = w;
        while (tmp) {
            int b = __ffs(tmp) - 1; tmp &= tmp - 1;
            lists[warp][k++] = (unsigned short)(lane * 32 + b);
        }
        __syncwarp();
        int j = 0;
        for (; j + 8 <= total; j += 8) {
            unsigned a0 = g_adj[lists[warp][j + 0] * 32 + lane];
            unsigned a1 = g_adj[lists[warp][j + 1] * 32 + lane];
            unsigned a2 = g_adj[lists[warp][j + 2] * 32 + lane];
            unsigned a3 = g_adj[lists[warp][j + 3] * 32 + lane];
            unsigned a4 = g_adj[lists[warp][j + 4] * 32 + lane];
            unsigned a5 = g_adj[lists[warp][j + 5] * 32 + lane];
            unsigned a6 = g_adj[lists[warp][j + 6] * 32 + lane];
            unsigned a7 = g_adj[lists[warp][j + 7] * 32 + lane];
            acc |= (a0 | a1) | (a2 | a3) | (a4 | a5) | (a6 | a7);
        }
        for (; j < total; j++) acc |= g_adj[lists[warp][j] * 32 + lane];
    } else {
        for (int ww = 0; ww < 32; ww++) {
            unsigned word = __shfl_sync(~0u, w, ww);
            while (word) {
                int b = __ffs(word) - 1; word &= word - 1;
                acc |= g_adj[(ww * 32 + b) * 32 + lane];
            }
        }
    }
    out[row * 32 + lane] = w & acc;
}

// topo bias table [2][8]
__global__ void ttab_kernel(const float* __restrict__ w1, const float* __restrict__ b1,
                            const float* __restrict__ w2, const float* __restrict__ b2) {
    int t = threadIdx.x;
    if (t < 16) {
        float pv = (float)(t >> 3);
        int h = t & 7;
        float acc = b2[h];
        for (int c = 0; c < 32; c++) {
            float hv = fmaf(pv, w1[c], b1[c]);
            float s = __fdividef(hv, 1.f + __expf(-hv));
            acc = fmaf(s, w2[c * 8 + h], acc);
        }
        g_ttab[t] = acc;
    }
}

// geo MLP lookup table, transposed layout [h][i]
__global__ void geo_table_kernel(const float* __restrict__ w1, const float* __restrict__ b1,
                                 const float* __restrict__ w2, const float* __restrict__ b2) {
    int i = blockIdx.x * 256 + threadIdx.x;
    if (i >= TBL_N) return;
    float dist = (float)i * (TBL_MAX / (float)(TBL_N - 1));
    float a[8];
#pragma unroll
    for (int h = 0; h < 8; h++) a[h] = b2[h];
    for (int c = 0; c < 32; c++) {
        float hv = fmaf(dist, w1[c], b1[c]);
        float s = __fdividef(hv, 1.f + __expf(-hv));
#pragma unroll
        for (int h = 0; h < 8; h++) a[h] = fmaf(s, w2[c * 8 + h], a[h]);
    }
#pragma unroll
    for (int h = 0; h < 8; h++) g_tbl[h * TBL_N + i] = a[h];
}

// -------- 128x64 tiled SGEMM body with FFMA2, C = [A0|A1]@B + bias [,silu] ---
__device__ __forceinline__ void gemm_body(
    const float* __restrict__ A0, const float* __restrict__ A1, int ksplit,
    int lda, const float* __restrict__ B, int ldb,
    const float* __restrict__ bias, float* __restrict__ C, int ldc, int K, int act)
{
    __shared__ float As[16][132];
    __shared__ float Bs[16][64];
    int tid = threadIdx.x;
    int tx = tid & 15, ty = tid >> 4;
    int row0 = blockIdx.y * 128, col0 = blockIdx.x * 64;
    ull acc2[4][4];
#pragma unroll
    for (int i = 0; i < 4; i++)
#pragma unroll
        for (int j = 0; j < 4; j++) acc2[i][j] = 0ull;

    int ar = tid >> 1, acq = (tid & 1) << 3;
    int bk = tid >> 4, bn = (tid & 15) << 2;

    for (int k0 = 0; k0 < K; k0 += 16) {
        const float* Ap = (k0 < ksplit)
            ? &A0[(row0 + ar) * lda + k0 + acq]
            : &A1[(row0 + ar) * lda + (k0 - ksplit) + acq];
        float4 av0 = *(const float4*)Ap;
        float4 av1 = *(const float4*)(Ap + 4);
        As[acq + 0][ar] = av0.x; As[acq + 1][ar] = av0.y;
        As[acq + 2][ar] = av0.z; As[acq + 3][ar] = av0.w;
        As[acq + 4][ar] = av1.x; As[acq + 5][ar] = av1.y;
        As[acq + 6][ar] = av1.z; As[acq + 7][ar] = av1.w;
        *(float4*)&Bs[bk][bn] = *(const float4*)&B[(k0 + bk) * ldb + col0 + bn];
        __syncthreads();
#pragma unroll
        for (int kk = 0; kk < 16; kk++) {
            ulonglong2 a01 = *(const ulonglong2*)&As[kk][ty << 3];
            ulonglong2 a23 = *(const ulonglong2*)&As[kk][(ty << 3) + 4];
            float4 b = *(const float4*)&Bs[kk][tx << 2];
            ull bb0 = pack2(b.x, b.x), bb1 = pack2(b.y, b.y);
            ull bb2 = pack2(b.z, b.z), bb3 = pack2(b.w, b.w);
            fma2(acc2[0][0], a01.x, bb0); fma2(acc2[0][1], a01.x, bb1);
            fma2(acc2[0][2], a01.x, bb2); fma2(acc2[0][3], a01.x, bb3);
            fma2(acc2[1][0], a01.y, bb0); fma2(acc2[1][1], a01.y, bb1);
            fma2(acc2[1][2], a01.y, bb2); fma2(acc2[1][3], a01.y, bb3);
            fma2(acc2[2][0], a23.x, bb0); fma2(acc2[2][1], a23.x, bb1);
            fma2(acc2[2][2], a23.x, bb2); fma2(acc2[2][3], a23.x, bb3);
            fma2(acc2[3][0], a23.y, bb0); fma2(acc2[3][1], a23.y, bb1);
            fma2(acc2[3][2], a23.y, bb2); fma2(acc2[3][3], a23.y, bb3);
        }
        __syncthreads();
    }
#pragma unroll
    for (int i2 = 0; i2 < 4; i2++) {
        int r = row0 + (ty << 3) + (i2 << 1);
#pragma unroll
        for (int j = 0; j < 4; j++) {
            int cc = col0 + (tx << 2) + j;
            float2 v = unpack2(acc2[i2][j]);
            float v0 = v.x + bias[cc];
            float v1 = v.y + bias[cc];
            if (act) {
                v0 = __fdividef(v0, 1.f + __expf(-v0));
                v1 = __fdividef(v1, 1.f + __expf(-v1));
            }
            C[r * ldc + cc] = v0;
            C[(r + 1) * ldc + cc] = v1;
        }
    }
}

__global__ __launch_bounds__(256) void sgemm128(
    const float* __restrict__ A0, const float* __restrict__ A1, int ksplit,
    int lda, const float* __restrict__ B, int ldb,
    const float* __restrict__ bias, float* __restrict__ C, int ldc, int K, int act)
{
    gemm_body(A0, A1, ksplit, lda, B, ldb, bias, C, ldc, K, act);
}

__global__ __launch_bounds__(256) void qkv_kernel(
    const float* __restrict__ src, const float* __restrict__ tgt,
    const float* __restrict__ Wq, const float* __restrict__ bq,
    const float* __restrict__ Wk, const float* __restrict__ bk,
    const float* __restrict__ Wv, const float* __restrict__ bv)
{
    int z = blockIdx.z;
    const float* A = (z == 0) ? src : tgt;
    const float* W = (z == 0) ? Wq : ((z == 1) ? Wk : Wv);
    const float* b = (z == 0) ? bq : ((z == 1) ? bk : bv);
    float* C = (z == 0) ? g_q : ((z == 1) ? g_k : g_v);
    gemm_body(A, A, 256, 256, W, 256, b, C, 256, 256, 0);
}

// gate logits: 2 dots of length 1024 per node, then 2-way softmax
__global__ __launch_bounds__(256) void gate2_kernel(const float* __restrict__ w2,
                                                    const float* __restrict__ b2) {
    int n = blockIdx.x, tid = threadIdx.x;
    const float* hrow = g_gateh + n * 1024;
    float s0 = 0.f, s1 = 0.f;
#pragma unroll
    for (int t = 0; t < 4; t++) {
        int j = tid + 256 * t;
        float hv = hrow[j];
        s0 = fmaf(hv, w2[j * 2 + 0], s0);
        s1 = fmaf(hv, w2[j * 2 + 1], s1);
    }
    for (int o = 16; o; o >>= 1) {
        s0 += __shfl_xor_sync(~0u, s0, o);
        s1 += __shfl_xor_sync(~0u, s1, o);
    }
    __shared__ float r0[8], r1[8];
    if ((tid & 31) == 0) { r0[tid >> 5] = s0; r1[tid >> 5] = s1; }
    __syncthreads();
    if (tid == 0) {
        float l0 = b2[0], l1 = b2[1];
        for (int j = 0; j < 8; j++) { l0 += r0[j]; l1 += r1[j]; }
        float m = fmaxf(l0, l1);
        float e0 = __expf(l0 - m), e1 = __expf(l1 - m);
        float inv = __fdividef(1.f, e0 + e1);
        g_gate[n * 2 + 0] = e0 * inv;
        g_gate[n * 2 + 1] = e1 * inv;
    }
}

// ============ fused flash attention: QK+bias -> online softmax -> PV =========
// block: 64 n-rows x 1 head; m-chunks of 64; warps 0-3 PV / warps 4-7 prefetch.
// smem float offsets:
#define FS_QS    0            // [64][36]
#define FS_KS    2304         // 2 x [64][36]
#define FS_VT    6912         // 3 x [32][68]  (v transposed [d][m])
#define FS_PS    13440        // [64][68]
#define FS_POSN  17792        // 192
#define FS_POSM  17984        // 2 x 192
#define FS_SG0   18368        // 64
#define FS_SG1   18432        // 64
#define FS_SSC   18496        // 64
#define FS_SS    18560        // 64
#define FS_TW    18624        // 2 x 128 (unsigned)
#define FLASH_SMEM ((18624 + 256) * 4)

__device__ __forceinline__ void flash_load_chunk(
    int cn, int h, int n0, int lt, int stride,
    float* __restrict__ sh, const float* __restrict__ pos)
{
    int m0 = cn * 64;
    float* ksb = sh + FS_KS + (cn & 1) * 2304;
    float* vtb = sh + FS_VT + (cn % 3) * 2176;
    float* pmb = sh + FS_POSM + (cn & 1) * 192;
    unsigned* twb = (unsigned*)(sh + FS_TW) + (cn & 1) * 128;
    for (int f = lt; f < 512; f += stride) {
        int row = f >> 3, c4 = (f & 7) << 2;
        *(float4*)&ksb[row * 36 + c4] =
            *(const float4*)&g_k[(m0 + row) * 256 + h * 32 + c4];
        float4 vv = *(const float4*)&g_v[(m0 + row) * 256 + h * 32 + c4];
        vtb[(c4 + 0) * 68 + row] = vv.x;
        vtb[(c4 + 1) * 68 + row] = vv.y;
        vtb[(c4 + 2) * 68 + row] = vv.z;
        vtb[(c4 + 3) * 68 + row] = vv.w;
    }
    for (int f = lt; f < 192; f += stride) pmb[f] = pos[m0 * 3 + f];
    for (int f = lt; f < 128; f += stride)
        twb[f] = g_pa[(n0 + (f >> 1)) * 32 + (m0 >> 5) + (f & 1)];
}

__global__ __launch_bounds__(256) void flash_kernel(const float* __restrict__ pos)
{
    extern __shared__ float sh[];
    int tid = threadIdx.x;
    int h = blockIdx.y, n0 = blockIdx.x * 64;
    const float qscale = 0.17677669529663687f;   // 1/sqrt(32)

    // --- static tile loads ---
#pragma unroll
    for (int r = 0; r < 2; r++) {
        int f = tid + 256 * r;
        int row = f >> 3, c4 = (f & 7) << 2;
        float4 v = *(const float4*)&g_q[(n0 + row) * 256 + h * 32 + c4];
        v.x *= qscale; v.y *= qscale; v.z *= qscale; v.w *= qscale;
        *(float4*)&sh[FS_QS + row * 36 + c4] = v;
    }
    if (tid < 192) sh[FS_POSN + tid] = pos[n0 * 3 + tid];
    if (tid < 64) {
        sh[FS_SG0 + tid] = g_gate[(n0 + tid) * 2 + 0];
        sh[FS_SG1 + tid] = g_gate[(n0 + tid) * 2 + 1];
    }
    float t0 = g_ttab[h], t1 = g_ttab[8 + h];
    flash_load_chunk(0, h, n0, tid, 256, sh, pos);

    float M_[4], S_[4];
#pragma unroll
    for (int i = 0; i < 4; i++) { M_[i] = -1e30f; S_[i] = 0.f; }
    float acc[4][4];
#pragma unroll
    for (int i = 0; i < 4; i++)
#pragma unroll
        for (int j = 0; j < 4; j++) acc[i][j] = 0.f;

    int ng = tid >> 4, mg = tid & 15;   // QK layout: rows ng*4+i, cols mg+16j
    int nr = tid >> 3, dg = tid & 7;    // PV layout (tid<128): rows nr+16k, d dg+8l

    __syncthreads();

    for (int c = 0; c <= 16; c++) {
        // -------- Phase A: PV(c-1) on warps 0-3 | prefetch(c+1) on warps 4-7
        if (tid < 128) {
            if (c > 0) {
                const float* vtb = sh + FS_VT + ((c - 1) % 3) * 2176;
                const float* psb = sh + FS_PS;
#pragma unroll
                for (int k = 0; k < 4; k++) {
                    float sc = sh[FS_SSC + nr + 16 * k];
#pragma unroll
                    for (int l = 0; l < 4; l++) acc[k][l] *= sc;
                }
                for (int m4 = 0; m4 < 64; m4 += 4) {
                    float4 pk[4], vl[4];
#pragma unroll
                    for (int k = 0; k < 4; k++)
                        pk[k] = *(const float4*)&psb[(nr + 16 * k) * 68 + m4];
#pragma unroll
                    for (int l = 0; l < 4; l++)
                        vl[l] = *(const float4*)&vtb[(dg + 8 * l) * 68 + m4];
#pragma unroll
                    for (int k = 0; k < 4; k++)
#pragma unroll
                        for (int l = 0; l < 4; l++)
                            acc[k][l] += pk[k].x * vl[l].x + pk[k].y * vl[l].y
                                       + pk[k].z * vl[l].z + pk[k].w * vl[l].w;
                }
            }
        } else {
            if (c + 1 < 16)
                flash_load_chunk(c + 1, h, n0, tid - 128, 128, sh, pos);
        }
        if (c == 16) break;
        __syncthreads();

        // -------- Phase B: QK + bias + online softmax + p-tile store (all warps)
        {
            const float* ksb = sh + FS_KS + (c & 1) * 2304;
            const float* pmb = sh + FS_POSM + (c & 1) * 192;
            const unsigned* twb = (const unsigned*)(sh + FS_TW) + (c & 1) * 128;
            float l[4][4];
#pragma unroll
            for (int i = 0; i < 4; i++)
#pragma unroll
                for (int j = 0; j < 4; j++) l[i][j] = 0.f;

            for (int d4 = 0; d4 < 32; d4 += 4) {
                float4 qv[4], kv[4];
#pragma unroll
                for (int i = 0; i < 4; i++)
                    qv[i] = *(const float4*)&sh[FS_QS + (ng * 4 + i) * 36 + d4];
#pragma unroll
                for (int j = 0; j < 4; j++)
                    kv[j] = *(const float4*)&ksb[(mg + 16 * j) * 36 + d4];
#pragma unroll
                for (int i = 0; i < 4; i++)
#pragma unroll
                    for (int j = 0; j < 4; j++)
                        l[i][j] += qv[i].x * kv[j].x + qv[i].y * kv[j].y
                                 + qv[i].z * kv[j].z + qv[i].w * kv[j].w;
            }
            // bias: gate0*geoTbl(dist) + gate1*topo
#pragma unroll
            for (int i = 0; i < 4; i++) {
                int n = ng * 4 + i;
                float pnx = sh[FS_POSN + n * 3 + 0];
                float pny = sh[FS_POSN + n * 3 + 1];
                float pnz = sh[FS_POSN + n * 3 + 2];
                float g0 = sh[FS_SG0 + n], g1 = sh[FS_SG1 + n];
                unsigned w0 = twb[n * 2 + 0], w1 = twb[n * 2 + 1];
#pragma unroll
                for (int j = 0; j < 4; j++) {
                    int m = mg + 16 * j;
                    float dx = pnx - pmb[m * 3 + 0];
                    float dy = pny - pmb[m * 3 + 1];
                    float dz = pnz - pmb[m * 3 + 2];
                    float dist = sqrtf(fmaxf(dx * dx + dy * dy + dz * dz, 1e-12f));
                    float tt = fminf(dist, TBL_MAX) * TBL_SCALE;
                    int i0 = (int)tt;
                    if (i0 > TBL_N - 2) i0 = TBL_N - 2;
                    float fr = tt - (float)i0;
                    float ta = __ldg(&g_tbl[h * TBL_N + i0]);
                    float tb = __ldg(&g_tbl[h * TBL_N + i0 + 1]);
                    float geo = ta + fr * (tb - ta);
                    unsigned bit = ((m < 32 ? w0 : w1) >> (m & 31)) & 1u;
                    l[i][j] += g0 * geo + g1 * (bit ? t1 : t0);
                }
            }
            // online softmax over this chunk; rows owned by 16-lane half-warps
#pragma unroll
            for (int i = 0; i < 4; i++) {
                float rm = fmaxf(fmaxf(l[i][0], l[i][1]), fmaxf(l[i][2], l[i][3]));
                rm = fmaxf(rm, __shfl_xor_sync(~0u, rm, 8));
                rm = fmaxf(rm, __shfl_xor_sync(~0u, rm, 4));
                rm = fmaxf(rm, __shfl_xor_sync(~0u, rm, 2));
                rm = fmaxf(rm, __shfl_xor_sync(~0u, rm, 1));
                float nM = fmaxf(M_[i], rm);
                float sc = __expf(M_[i] - nM);
                float ls = 0.f;
#pragma unroll
                for (int j = 0; j < 4; j++) {
                    float p = __expf(l[i][j] - nM);
                    l[i][j] = p;
                    ls += p;
                }
                ls += __shfl_xor_sync(~0u, ls, 8);
                ls += __shfl_xor_sync(~0u, ls, 4);
                ls += __shfl_xor_sync(~0u, ls, 2);
                ls += __shfl_xor_sync(~0u, ls, 1);
                S_[i] = S_[i] * sc + ls;
                M_[i] = nM;
                if (mg == 0) {
                    sh[FS_SSC + ng * 4 + i] = sc;
                    sh[FS_SS + ng * 4 + i] = S_[i];
                }
            }
            // store p tile
#pragma unroll
            for (int i = 0; i < 4; i++)
#pragma unroll
                for (int j = 0; j < 4; j++)
                    sh[FS_PS + (ng * 4 + i) * 68 + mg + 16 * j] = l[i][j];
        }
        __syncthreads();
    }

    // -------- writeout
    if (tid < 128) {
#pragma unroll
        for (int k = 0; k < 4; k++) {
            int n = nr + 16 * k;
            float inv = __fdividef(1.f, sh[FS_SS + n]);
#pragma unroll
            for (int l = 0; l < 4; l++)
                g_attnout[(n0 + n) * 256 + h * 32 + dg + 8 * l] = acc[k][l] * inv;
        }
    }
}

// ---------------- residual + layernorm ----------------------------------------
__global__ __launch_bounds__(256) void ln_kernel(const float* __restrict__ src,
                                                 const float* __restrict__ g,
                                                 const float* __restrict__ b,
                                                 float* __restrict__ out) {
    int n = blockIdx.x, tid = threadIdx.x;
    float x = src[n * 256 + tid] + g_proj[n * 256 + tid];
    float s = x;
    for (int o = 16; o; o >>= 1) s += __shfl_xor_sync(~0u, s, o);
    __shared__ float r1[8], r2[8];
    if ((tid & 31) == 0) r1[tid >> 5] = s;
    __syncthreads();
    float tot = 0.f;
#pragma unroll
    for (int j = 0; j < 8; j++) tot += r1[j];
    float mu = tot * (1.f / 256.f);
    float d = x - mu;
    float s2 = d * d;
    for (int o = 16; o; o >>= 1) s2 += __shfl_xor_sync(~0u, s2, o);
    if ((tid & 31) == 0) r2[tid >> 5] = s2;
    __syncthreads();
    float var = 0.f;
#pragma unroll
    for (int j = 0; j < 8; j++) var += r2[j];
    var *= (1.f / 256.f);
    out[n * 256 + tid] = d * rsqrtf(var + 1e-5f) * g[tid] + b[tid];
}

// ---------------- launch ------------------------------------------------------
extern "C" void kernel_launch(void* const* d_in, const int* in_sizes, int n_in,
                              void* d_out, int out_size) {
    const float* src_feat = (const float*)d_in[0];
    const float* tgt_feat = (const float*)d_in[1];
    const float* src_pos  = (const float*)d_in[2];
    const void*  edges    = d_in[3];
    const float* Wq = (const float*)d_in[4],  *bq = (const float*)d_in[5];
    const float* Wk = (const float*)d_in[6],  *bk = (const float*)d_in[7];
    const float* Wv = (const float*)d_in[8],  *bv = (const float*)d_in[9];
    const float* geo_w1 = (const float*)d_in[10], *geo_b1 = (const float*)d_in[11];
    const float* geo_w2 = (const float*)d_in[12], *geo_b2 = (const float*)d_in[13];
    const float* top_w1 = (const float*)d_in[14], *top_b1 = (const float*)d_in[15];
    const float* top_w2 = (const float*)d_in[16], *top_b2 = (const float*)d_in[17];
    const float* gate_w1 = (const float*)d_in[18], *gate_b1 = (const float*)d_in[19];
    const float* gate_w2 = (const float*)d_in[20], *gate_b2 = (const float*)d_in[21];
    const float* Wo = (const float*)d_in[22], *bo = (const float*)d_in[23];
    const float* ln_g = (const float*)d_in[24], *ln_b = (const float*)d_in[25];
    float* out = (float*)d_out;

    void *pgateh, *pattn, *pproj;
    cudaGetSymbolAddress(&pgateh, g_gateh);
    cudaGetSymbolAddress(&pattn, g_attnout);
    cudaGetSymbolAddress(&pproj, g_proj);

    cudaFuncSetAttribute(flash_kernel,
                         cudaFuncAttributeMaxDynamicSharedMemorySize, FLASH_SMEM);

    // setup (ordered so ncu -s5 -c1 captures qkv_kernel as launch #6)
    ttab_kernel<<<1, 16>>>(top_w1, top_b1, top_w2, top_b2);
    geo_table_kernel<<<32, 256>>>(geo_w1, geo_b1, geo_w2, geo_b2);
    detect_kernel<<<1, 1>>>((const unsigned*)edges);
    zero_adj_kernel<<<128, 256>>>();
    scatter_edges_kernel<<<64, 256>>>(edges);

    // q/k/v projections (launch #6 for profiling)
    qkv_kernel<<<dim3(4, 8, 3), 256>>>(src_feat, tgt_feat, Wq, bq, Wk, bk, Wv, bv);

    // path propagation (binary bitsets)
    path_round_kernel<<<128, 256>>>(0);
    path_round_kernel<<<128, 256>>>(1);
    path_round_kernel<<<128, 256>>>(2);   // final path in g_pa

    // gate MLP (split-K concat folded into GEMM)
    sgemm128<<<dim3(16, 8), 256>>>(src_feat, tgt_feat, 256, 256, gate_w1, 1024,
                                   gate_b1, (float*)pgateh, 1024, 512, 1);
    gate2_kernel<<<1024, 256>>>(gate_w2, gate_b2);

    // fused attention
    flash_kernel<<<dim3(16, 8), 256, FLASH_SMEM>>>(src_pos);

    // output projection + residual + layernorm
    sgemm128<<<dim3(4, 8), 256>>>((const float*)pattn, (const float*)pattn, 256, 256,
                                  Wo, 256, bo, (float*)pproj, 256, 256, 0);
    ln_kernel<<<1024, 256>>>(src_feat, ln_g, ln_b, out);
}

// round 9
// speedup vs baseline: 1.0987x; 1.0987x over previous
#include <cuda_runtime.h>
#include <cuda_bf16.h>

#define NN 1024
#define HID 256
#define NH 8
#define HD 32
#define NE 16384

#define TBL_N 8192
#define TBL_MAX 24.0f
#define TBL_SCALE ((float)(TBL_N - 1) / TBL_MAX)

// ---------------- scratch (static device memory; no allocations) -------------
__device__ float    g_q[NN * HID];
__device__ float    g_k[NN * HID];
__device__ float    g_v[NN * HID];
__device__ float    g_gateh[NN * 4 * HID];
__device__ float    g_gate[NN * 2];
__device__ unsigned g_adj[NN * 32];
__device__ unsigned g_pa[NN * 32];
__device__ unsigned g_pb[NN * 32];
__device__ float    g_ttab[16];                  // [path_val(0/1)][head]
__device__ float    g_tbl[TBL_N * 8];            // geo MLP lookup table [i][h]
__device__ float    g_logits[NN * NH * NN];      // 32 MB, [n][h][m], raw logits
__device__ float2   g_stats[NN * NH];            // per-row (max, 1/sum)
__device__ float    g_attnout[NN * HID];
__device__ float    g_proj[NN * HID];

// ------- setup: geo table (blocks 0-31) + zero adj slices + ttab (block 32) --
__global__ void setup_kernel(const float* __restrict__ gw1, const float* __restrict__ gb1,
                             const float* __restrict__ gw2, const float* __restrict__ gb2,
                             const float* __restrict__ tw1, const float* __restrict__ tb1,
                             const float* __restrict__ tw2, const float* __restrict__ tb2) {
    int b = blockIdx.x, tid = threadIdx.x;
    if (b < 32) {
        // zero a 1024-word slice of g_adj
#pragma unroll
        for (int t = 0; t < 4; t++) g_adj[b * 1024 + tid + 256 * t] = 0u;
        // geo MLP table entry
        int i = b * 256 + tid;
        float dist = (float)i * (TBL_MAX / (float)(TBL_N - 1));
        float a[8];
#pragma unroll
        for (int h = 0; h < 8; h++) a[h] = gb2[h];
        for (int c = 0; c < 32; c++) {
            float hv = fmaf(dist, gw1[c], gb1[c]);
            float s = __fdividef(hv, 1.f + __expf(-hv));
#pragma unroll
            for (int h = 0; h < 8; h++) a[h] = fmaf(s, gw2[c * 8 + h], a[h]);
        }
#pragma unroll
        for (int h = 0; h < 8; h++) g_tbl[i * 8 + h] = a[h];
    } else {
        // topo bias table [2][8]
        if (tid < 16) {
            float pv = (float)(tid >> 3);
            int h = tid & 7;
            float acc = tb2[h];
            for (int c = 0; c < 32; c++) {
                float hv = fmaf(pv, tw1[c], tb1[c]);
                float s = __fdividef(hv, 1.f + __expf(-hv));
                acc = fmaf(s, tw2[c * 8 + h], acc);
            }
            g_ttab[tid] = acc;
        }
    }
}

// ---------------- scatter edges with inline dtype detect ----------------------
// Values are in [0,1024). If stored little-endian int64, odd 32-bit words of the
// first 8 entries are all 0. If int32, each odd word is a uniform index;
// P(8 consecutive zeros) = 1024^-8.
__global__ void scatter_edges_kernel(const unsigned* __restrict__ w) {
    bool is64 = true;
#pragma unroll
    for (int i = 1; i < 16; i += 2) is64 &= (w[i] == 0u);
    int e = blockIdx.x * blockDim.x + threadIdx.x;
    if (e >= NE) return;
    int s, d;
    if (is64) {
        const long long* p = (const long long*)w;
        s = (int)p[e];
        d = (int)p[NE + e];
    } else {
        const int* p = (const int*)w;
        s = p[e];
        d = p[NE + e];
    }
    atomicOr(&g_adj[s * 32 + (d >> 5)], 1u << (d & 31));
}

// path = min(path, path @ adj): binary reachability step on bitsets.
#define LIST_CAP 512
__global__ __launch_bounds__(256) void path_round_kernel(int r) {
    const unsigned* in = (r == 0) ? g_adj : ((r == 1) ? g_pa : g_pb);
    unsigned* out = (r == 1) ? g_pb : g_pa;
    __shared__ unsigned short lists[8][LIST_CAP];
    int warp = threadIdx.x >> 5, lane = threadIdx.x & 31;
    int row = blockIdx.x * 8 + warp;
    unsigned w = in[row * 32 + lane];
    int c = __popc(w);
    int pre = c;
#pragma unroll
    for (int o = 1; o < 32; o <<= 1) {
        int x = __shfl_up_sync(~0u, pre, o);
        if (lane >= o) pre += x;
    }
    int total = __shfl_sync(~0u, pre, 31);
    unsigned acc = 0u;
    if (total <= LIST_CAP) {
        int k = pre - c;
        unsigned tmp = w;
        while (tmp) {
            int b = __ffs(tmp) - 1; tmp &= tmp - 1;
            lists[warp][k++] = (unsigned short)(lane * 32 + b);
        }
        __syncwarp();
        int j = 0;
        for (; j + 8 <= total; j += 8) {
            unsigned a0 = g_adj[lists[warp][j + 0] * 32 + lane];
            unsigned a1 = g_adj[lists[warp][j + 1] * 32 + lane];
            unsigned a2 = g_adj[lists[warp][j + 2] * 32 + lane];
            unsigned a3 = g_adj[lists[warp][j + 3] * 32 + lane];
            unsigned a4 = g_adj[lists[warp][j + 4] * 32 + lane];
            unsigned a5 = g_adj[lists[warp][j + 5] * 32 + lane];
            unsigned a6 = g_adj[lists[warp][j + 6] * 32 + lane];
            unsigned a7 = g_adj[lists[warp][j + 7] * 32 + lane];
            acc |= (a0 | a1) | (a2 | a3) | (a4 | a5) | (a6 | a7);
        }
        for (; j < total; j++) acc |= g_adj[lists[warp][j] * 32 + lane];
    } else {
        for (int ww = 0; ww < 32; ww++) {
            unsigned word = __shfl_sync(~0u, w, ww);
            while (word) {
                int b = __ffs(word) - 1; word &= word - 1;
                acc |= g_adj[(ww * 32 + b) * 32 + lane];
            }
        }
    }
    out[row * 32 + lane] = w & acc;
}

// ---------------- 64x64 tiled SGEMM body, C = [A0|A1]@B + bias [, silu] ------
__device__ __forceinline__ void gemm_body(
    const float* __restrict__ A0, const float* __restrict__ A1, int ksplit,
    int lda, const float* __restrict__ B, int ldb,
    const float* __restrict__ bias, float* __restrict__ C, int ldc, int K, int act)
{
    __shared__ float As[16][68];
    __shared__ float Bs[16][64];
    int tid = threadIdx.x;
    int tx = tid & 15, ty = tid >> 4;
    int row0 = blockIdx.y * 64, col0 = blockIdx.x * 64;
    float acc[4][4];
#pragma unroll
    for (int i = 0; i < 4; i++)
#pragma unroll
        for (int j = 0; j < 4; j++) acc[i][j] = 0.f;
    int ar = tid >> 2, ac = (tid & 3) << 2;
    int bk = tid >> 4, bn = (tid & 15) << 2;
    for (int k0 = 0; k0 < K; k0 += 16) {
        const float* Ap = (k0 < ksplit)
            ? &A0[(row0 + ar) * lda + k0 + ac]
            : &A1[(row0 + ar) * lda + (k0 - ksplit) + ac];
        float4 av = *(const float4*)Ap;
        As[ac + 0][ar] = av.x; As[ac + 1][ar] = av.y;
        As[ac + 2][ar] = av.z; As[ac + 3][ar] = av.w;
        *(float4*)&Bs[bk][bn] = *(const float4*)&B[(k0 + bk) * ldb + col0 + bn];
        __syncthreads();
#pragma unroll
        for (int kk = 0; kk < 16; kk++) {
            float4 a = *(const float4*)&As[kk][ty << 2];
            float4 b = *(const float4*)&Bs[kk][tx << 2];
            acc[0][0] = fmaf(a.x, b.x, acc[0][0]); acc[0][1] = fmaf(a.x, b.y, acc[0][1]);
            acc[0][2] = fmaf(a.x, b.z, acc[0][2]); acc[0][3] = fmaf(a.x, b.w, acc[0][3]);
            acc[1][0] = fmaf(a.y, b.x, acc[1][0]); acc[1][1] = fmaf(a.y, b.y, acc[1][1]);
            acc[1][2] = fmaf(a.y, b.z, acc[1][2]); acc[1][3] = fmaf(a.y, b.w, acc[1][3]);
            acc[2][0] = fmaf(a.z, b.x, acc[2][0]); acc[2][1] = fmaf(a.z, b.y, acc[2][1]);
            acc[2][2] = fmaf(a.z, b.z, acc[2][2]); acc[2][3] = fmaf(a.z, b.w, acc[2][3]);
            acc[3][0] = fmaf(a.w, b.x, acc[3][0]); acc[3][1] = fmaf(a.w, b.y, acc[3][1]);
            acc[3][2] = fmaf(a.w, b.z, acc[3][2]); acc[3][3] = fmaf(a.w, b.w, acc[3][3]);
        }
        __syncthreads();
    }
#pragma unroll
    for (int i = 0; i < 4; i++) {
        int r = row0 + (ty << 2) + i;
#pragma unroll
        for (int j = 0; j < 4; j++) {
            int cc = col0 + (tx << 2) + j;
            float v = acc[i][j] + bias[cc];
            if (act) v = __fdividef(v, 1.f + __expf(-v));
            C[r * ldc + cc] = v;
        }
    }
}

__global__ __launch_bounds__(256) void sgemm64(
    const float* __restrict__ A0, const float* __restrict__ A1, int ksplit,
    int lda, const float* __restrict__ B, int ldb,
    const float* __restrict__ bias, float* __restrict__ C, int ldc, int K, int act)
{
    gemm_body(A0, A1, ksplit, lda, B, ldb, bias, C, ldc, K, act);
}

// q/k/v projections fused via blockIdx.z
__global__ __launch_bounds__(256) void qkv_kernel(
    const float* __restrict__ src, const float* __restrict__ tgt,
    const float* __restrict__ Wq, const float* __restrict__ bq,
    const float* __restrict__ Wk, const float* __restrict__ bk,
    const float* __restrict__ Wv, const float* __restrict__ bv)
{
    int z = blockIdx.z;
    const float* A = (z == 0) ? src : tgt;
    const float* W = (z == 0) ? Wq : ((z == 1) ? Wk : Wv);
    const float* b = (z == 0) ? bq : ((z == 1) ? bk : bv);
    float* C = (z == 0) ? g_q : ((z == 1) ? g_k : g_v);
    gemm_body(A, A, 256, 256, W, 256, b, C, 256, 256, 0);
}

// gate logits: 2 dots of length 1024 per node, then 2-way softmax
__global__ __launch_bounds__(256) void gate2_kernel(const float* __restrict__ w2,
                                                    const float* __restrict__ b2) {
    int n = blockIdx.x, tid = threadIdx.x;
    const float* hrow = g_gateh + n * 1024;
    float s0 = 0.f, s1 = 0.f;
#pragma unroll
    for (int t = 0; t < 4; t++) {
        int j = tid + 256 * t;
        float hv = hrow[j];
        s0 = fmaf(hv, w2[j * 2 + 0], s0);
        s1 = fmaf(hv, w2[j * 2 + 1], s1);
    }
    for (int o = 16; o; o >>= 1) {
        s0 += __shfl_xor_sync(~0u, s0, o);
        s1 += __shfl_xor_sync(~0u, s1, o);
    }
    __shared__ float r0[8], r1[8];
    if ((tid & 31) == 0) { r0[tid >> 5] = s0; r1[tid >> 5] = s1; }
    __syncthreads();
    if (tid == 0) {
        float l0 = b2[0], l1 = b2[1];
        for (int j = 0; j < 8; j++) { l0 += r0[j]; l1 += r1[j]; }
        float m = fmaxf(l0, l1);
        float e0 = __expf(l0 - m), e1 = __expf(l1 - m);
        float inv = __fdividef(1.f, e0 + e1);
        g_gate[n * 2 + 0] = e0 * inv;
        g_gate[n * 2 + 1] = e1 * inv;
    }
}

// ---------------- fused logits: QK/sqrt(D) + gate0*geoTbl(dist) + gate1*topo -
#define QPAD 260
#define LOGITS_SMEM ((64 * QPAD + 320) * 4)

__global__ __launch_bounds__(256) void logits_kernel(const float* __restrict__ pos)
{
    extern __shared__ float sh[];
    float* qs  = sh;                       // 32 x 260
    float* ks  = sh + 32 * QPAD;           // 32 x 260
    float* ext = sh + 64 * QPAD;
    float* sg0 = ext;                      // 32
    float* sg1 = sg0 + 32;                 // 32
    float* spn = sg1 + 32;                 // 32*3
    float* spm = spn + 96;                 // 32*3
    float* stt = spm + 96;                 // 16
    unsigned* spw = (unsigned*)(stt + 16); // 32

    int tid = threadIdx.x;
    int m0 = blockIdx.x * 32, n0 = blockIdx.y * 32;

#pragma unroll
    for (int t = 0; t < 8; t++) {
        int lin = tid + 256 * t;
        int r = lin >> 6, c4 = (lin & 63) << 2;
        *(float4*)&qs[r * QPAD + c4] = *(const float4*)&g_q[(n0 + r) * 256 + c4];
        *(float4*)&ks[r * QPAD + c4] = *(const float4*)&g_k[(m0 + r) * 256 + c4];
    }
    if (tid < 32) {
        sg0[tid] = g_gate[(n0 + tid) * 2 + 0];
        sg1[tid] = g_gate[(n0 + tid) * 2 + 1];
        spw[tid] = g_pa[(n0 + tid) * 32 + blockIdx.x];
        spn[tid * 3 + 0] = pos[(n0 + tid) * 3 + 0];
        spn[tid * 3 + 1] = pos[(n0 + tid) * 3 + 1];
        spn[tid * 3 + 2] = pos[(n0 + tid) * 3 + 2];
        spm[tid * 3 + 0] = pos[(m0 + tid) * 3 + 0];
        spm[tid * 3 + 1] = pos[(m0 + tid) * 3 + 1];
        spm[tid * 3 + 2] = pos[(m0 + tid) * 3 + 2];
    }
    if (tid < 16) stt[tid] = g_ttab[tid];
    __syncthreads();

    int mi = tid & 31, nbase = tid >> 5;
    float res[4][8];
    float px = spm[mi * 3 + 0], py = spm[mi * 3 + 1], pz = spm[mi * 3 + 2];

#pragma unroll
    for (int i = 0; i < 4; i++) {
        int ni = nbase + 8 * i;
        float dx = spn[ni * 3 + 0] - px;
        float dy = spn[ni * 3 + 1] - py;
        float dz = spn[ni * 3 + 2] - pz;
        float dist = sqrtf(fmaxf(dx * dx + dy * dy + dz * dz, 1e-12f));
        float gv0 = sg0[ni], gv1 = sg1[ni];
        int bit = (spw[ni] >> mi) & 1;

        float t = fminf(dist, TBL_MAX) * TBL_SCALE;
        int i0 = (int)t;
        if (i0 > TBL_N - 2) i0 = TBL_N - 2;
        float fr = t - (float)i0;
        const float4* tb = (const float4*)&g_tbl[i0 * 8];
        float4 r0 = __ldg(tb + 0), r1 = __ldg(tb + 1);
        float4 r2 = __ldg(tb + 2), r3 = __ldg(tb + 3);
        float a[8];
        a[0] = r0.x + fr * (r2.x - r0.x); a[1] = r0.y + fr * (r2.y - r0.y);
        a[2] = r0.z + fr * (r2.z - r0.z); a[3] = r0.w + fr * (r2.w - r0.w);
        a[4] = r1.x + fr * (r3.x - r1.x); a[5] = r1.y + fr * (r3.y - r1.y);
        a[6] = r1.z + fr * (r3.z - r1.z); a[7] = r1.w + fr * (r3.w - r1.w);
#pragma unroll
        for (int h = 0; h < 8; h++)
            res[i][h] = gv0 * a[h] + gv1 * stt[bit * 8 + h];
    }

    const float scale = 0.17677669529663687f;   // 1/sqrt(32)
#pragma unroll
    for (int h = 0; h < 8; h++) {
        float4 kr[8];
#pragma unroll
        for (int j = 0; j < 8; j++)
            kr[j] = *(const float4*)&ks[mi * QPAD + h * 32 + j * 4];
#pragma unroll
        for (int i = 0; i < 4; i++) {
            int ni = nbase + 8 * i;
            float s = 0.f;
#pragma unroll
            for (int j = 0; j < 8; j++) {
                float4 qv = *(const float4*)&qs[ni * QPAD + h * 32 + j * 4];
                s += qv.x * kr[j].x + qv.y * kr[j].y + qv.z * kr[j].z + qv.w * kr[j].w;
            }
            res[i][h] = fmaf(s, scale, res[i][h]);
        }
    }

#pragma unroll
    for (int i = 0; i < 4; i++) {
        int ng = n0 + nbase + 8 * i;
#pragma unroll
        for (int h = 0; h < 8; h++)
            g_logits[(ng * 8 + h) * 1024 + m0 + mi] = res[i][h];
    }
}

// ---------------- row stats (max, 1/sum of exp) -------------------------------
__global__ __launch_bounds__(256) void stats_kernel() {
    int row = blockIdx.x;
    const float* p = g_logits + (long)row * 1024;
    int tid = threadIdx.x;
    float4 v = *(const float4*)&p[tid * 4];
    float mx = fmaxf(fmaxf(v.x, v.y), fmaxf(v.z, v.w));
    for (int o = 16; o; o >>= 1) mx = fmaxf(mx, __shfl_xor_sync(~0u, mx, o));
    __shared__ float rm[8], rs[8];
    if ((tid & 31) == 0) rm[tid >> 5] = mx;
    __syncthreads();
    mx = rm[0];
#pragma unroll
    for (int j = 1; j < 8; j++) mx = fmaxf(mx, rm[j]);
    float s = __expf(v.x - mx) + __expf(v.y - mx) + __expf(v.z - mx) + __expf(v.w - mx);
    for (int o = 16; o; o >>= 1) s += __shfl_xor_sync(~0u, s, o);
    if ((tid & 31) == 0) rs[tid >> 5] = s;
    __syncthreads();
    if (tid == 0) {
        float tot = 0.f;
#pragma unroll
        for (int j = 0; j < 8; j++) tot += rs[j];
        g_stats[row] = make_float2(mx, __fdividef(1.f, tot));
    }
}

// -------- PV with inline softmax: out[n,h*32+d] = sum_m p[n,h,m] v[m,h*32+d] -
__global__ __launch_bounds__(256) void pv_kernel() {
    int h = blockIdx.x, n0 = blockIdx.y * 64;
    __shared__ float As[64][36];   // n x m (softmaxed probs)
    __shared__ float Bs[32][32];   // m x d
    __shared__ float2 sstat[64];
    int tid = threadIdx.x;
    int dxi = tid & 31;
    int ty = tid >> 5;
    if (tid < 64) sstat[tid] = g_stats[(n0 + tid) * 8 + h];
    __syncthreads();
    float acc[8];
#pragma unroll
    for (int i = 0; i < 8; i++) acc[i] = 0.f;

    for (int m0 = 0; m0 < 1024; m0 += 32) {
#pragma unroll
        for (int t = 0; t < 2; t++) {
            int lin = tid + 256 * t;
            int r = lin >> 3, c4 = (lin & 7) << 2;
            float4 v = *(const float4*)&g_logits[((long)(n0 + r) * 8 + h) * 1024 + m0 + c4];
            float2 st = sstat[r];
            v.x = __expf(v.x - st.x) * st.y;
            v.y = __expf(v.y - st.x) * st.y;
            v.z = __expf(v.z - st.x) * st.y;
            v.w = __expf(v.w - st.x) * st.y;
            *(float4*)&As[r][c4] = v;
        }
        {
            int r = tid >> 3, c4 = (tid & 7) << 2;
            *(float4*)&Bs[r][c4] = *(const float4*)&g_v[(m0 + r) * 256 + h * 32 + c4];
        }
        __syncthreads();
#pragma unroll
        for (int mm = 0; mm < 32; mm += 4) {
            float b0 = Bs[mm + 0][dxi], b1 = Bs[mm + 1][dxi];
            float b2 = Bs[mm + 2][dxi], b3 = Bs[mm + 3][dxi];
#pragma unroll
            for (int i = 0; i < 8; i++) {
                float4 a = *(const float4*)&As[ty + 8 * i][mm];
                acc[i] = fmaf(a.x, b0, fmaf(a.y, b1, fmaf(a.z, b2, fmaf(a.w, b3, acc[i]))));
            }
        }
        __syncthreads();
    }
#pragma unroll
    for (int i = 0; i < 8; i++)
        g_attnout[(n0 + ty + 8 * i) * 256 + h * 32 + dxi] = acc[i];
}

// ---------------- residual + layernorm ----------------------------------------
__global__ __launch_bounds__(256) void ln_kernel(const float* __restrict__ src,
                                                 const float* __restrict__ g,
                                                 const float* __restrict__ b,
                                                 float* __restrict__ out) {
    int n = blockIdx.x, tid = threadIdx.x;
    float x = src[n * 256 + tid] + g_proj[n * 256 + tid];
    float s = x;
    for (int o = 16; o; o >>= 1) s += __shfl_xor_sync(~0u, s, o);
    __shared__ float r1[8], r2[8];
    if ((tid & 31) == 0) r1[tid >> 5] = s;
    __syncthreads();
    float tot = 0.f;
#pragma unroll
    for (int j = 0; j < 8; j++) tot += r1[j];
    float mu = tot * (1.f / 256.f);
    float d = x - mu;
    float s2 = d * d;
    for (int o = 16; o; o >>= 1) s2 += __shfl_xor_sync(~0u, s2, o);
    if ((tid & 31) == 0) r2[tid >> 5] = s2;
    __syncthreads();
    float var = 0.f;
#pragma unroll
    for (int j = 0; j < 8; j++) var += r2[j];
    var *= (1.f / 256.f);
    out[n * 256 + tid] = d * rsqrtf(var + 1e-5f) * g[tid] + b[tid];
}

// ---------------- launch ------------------------------------------------------
extern "C" void kernel_launch(void* const* d_in, const int* in_sizes, int n_in,
                              void* d_out, int out_size) {
    const float* src_feat = (const float*)d_in[0];
    const float* tgt_feat = (const float*)d_in[1];
    const float* src_pos  = (const float*)d_in[2];
    const void*  edges    = d_in[3];
    const float* Wq = (const float*)d_in[4],  *bq = (const float*)d_in[5];
    const float* Wk = (const float*)d_in[6],  *bk = (const float*)d_in[7];
    const float* Wv = (const float*)d_in[8],  *bv = (const float*)d_in[9];
    const float* geo_w1 = (const float*)d_in[10], *geo_b1 = (const float*)d_in[11];
    const float* geo_w2 = (const float*)d_in[12], *geo_b2 = (const float*)d_in[13];
    const float* top_w1 = (const float*)d_in[14], *top_b1 = (const float*)d_in[15];
    const float* top_w2 = (const float*)d_in[16], *top_b2 = (const float*)d_in[17];
    const float* gate_w1 = (const float*)d_in[18], *gate_b1 = (const float*)d_in[19];
    const float* gate_w2 = (const float*)d_in[20], *gate_b2 = (const float*)d_in[21];
    const float* Wo = (const float*)d_in[22], *bo = (const float*)d_in[23];
    const float* ln_g = (const float*)d_in[24], *ln_b = (const float*)d_in[25];
    float* out = (float*)d_out;

    void *pgateh, *pattn, *pproj;
    cudaGetSymbolAddress(&pgateh, g_gateh);
    cudaGetSymbolAddress(&pattn, g_attnout);
    cudaGetSymbolAddress(&pproj, g_proj);

    cudaFuncSetAttribute(logits_kernel,
                         cudaFuncAttributeMaxDynamicSharedMemorySize, LOGITS_SMEM);

    // 1: geo table + zero adj + ttab (fused setup)
    setup_kernel<<<33, 256>>>(geo_w1, geo_b1, geo_w2, geo_b2,
                              top_w1, top_b1, top_w2, top_b2);
    // 2: scatter edges (inline dtype detect)
    scatter_edges_kernel<<<64, 256>>>((const unsigned*)edges);
    // 3: path round 1
    path_round_kernel<<<128, 256>>>(0);
    // 4: gate MLP GEMM (the big one — positioned for ncu capture)
    sgemm64<<<dim3(16, 16), 256>>>(src_feat, tgt_feat, 256, 256, gate_w1, 1024,
                                   gate_b1, (float*)pgateh, 1024, 512, 1);
    // 5-6: path rounds 2,3 (final path in g_pa)
    path_round_kernel<<<128, 256>>>(1);
    path_round_kernel<<<128, 256>>>(2);
    // 7: q/k/v projections
    qkv_kernel<<<dim3(4, 16, 3), 256>>>(src_feat, tgt_feat, Wq, bq, Wk, bk, Wv, bv);
    // 8: gate head + 2-way softmax
    gate2_kernel<<<1024, 256>>>(gate_w2, gate_b2);
    // 9-11: fused logits, row stats, PV
    logits_kernel<<<dim3(32, 32), 256, LOGITS_SMEM>>>(src_pos);
    stats_kernel<<<8192, 256>>>();
    pv_kernel<<<dim3(8, 16), 256>>>();
    // 12: output projection
    sgemm64<<<dim3(4, 16), 256>>>((const float*)pattn, (const float*)pattn, 256, 256,
                                  Wo, 256, bo, (float*)pproj, 256, 256, 0);
    // 13: residual + layernorm
    ln_kernel<<<1024, 256>>>(src_feat, ln_g, ln_b, out);
}